// round 6
// baseline (speedup 1.0000x reference)
#include <cuda_runtime.h>

#define BB 64
#define HH 256
#define WW 256
#define CC 3
#define KK 20
#define HWPIX (HH * WW)
#define WBLK_PER_IMG 128   // k_warp: each block covers 2 rows (512 pixels)

// Scratch (device global: allowed, no allocation)
__device__ float g_partial[BB][WBLK_PER_IMG][3];

// ---------------------------------------------------------------------------
// Kernel 1: direct-gather affine bilinear warp + per-block partial sums
// Interior fast path removes per-corner valid/clamp ALU for ~97% of pixels.
// ---------------------------------------------------------------------------
__global__ __launch_bounds__(256) void k_warp(
    const float* __restrict__ img,
    const float* __restrict__ zoom, const float* __restrict__ rot,
    const float* __restrict__ shy,  const float* __restrict__ ty,
    const float* __restrict__ tx,
    float* __restrict__ out)
{
    const int b   = blockIdx.y;
    const int blk = blockIdx.x;          // 0..127
    const int t   = threadIdx.x;         // 0..255

    const float z  = zoom[b];
    const float r  = rot[b];
    const float sh = shy[b];
    const float co = cosf(r), si = sinf(r);
    const float a0 = z * co;
    const float a1 = -z * (si + sh);
    const float b0 = z * si;
    const float b1 = z * co;
    const float cx = (WW - 1) * 0.5f, cy = (HH - 1) * 0.5f;
    const float a2 = -a0 * cx - a1 * cy + cx + tx[b];
    const float b2 = -b0 * cx - b1 * cy + cy + ty[b];

    const float* __restrict__ imgb = img + (size_t)b * HWPIX * CC;
    float* __restrict__ outb = out + (size_t)b * HWPIX * CC;

    float s0 = 0.f, s1 = 0.f, s2 = 0.f;

#pragma unroll
    for (int pp = 0; pp < 2; pp++) {
        const int p = blk * 512 + pp * 256 + t;   // pixel index within image
        const int y = p >> 8;                     // W == 256
        const int x = p & 255;

        const float xf = (float)x, yf = (float)y;
        const float xs = a0 * xf + a1 * yf + a2;
        const float ys = b0 * xf + b1 * yf + b2;
        const float x0f = floorf(xs);
        const float y0f = floorf(ys);
        const float wx = xs - x0f;
        const float wy = ys - y0f;
        const int x0i = (int)x0f;
        const int y0i = (int)y0f;

        const float w00 = (1.f - wy) * (1.f - wx);
        const float w01 = (1.f - wy) * wx;
        const float w10 = wy * (1.f - wx);
        const float w11 = wy * wx;

        float o0, o1, o2;

        const bool interior = (x0i >= 0) & (y0i >= 0) &
                              (x0i < WW - 1) & (y0i < HH - 1);
        if (interior) {
            const float* p00 = imgb + (y0i * WW + x0i) * CC;
            const float* p10 = p00 + WW * CC;
            o0 = w00 * p00[0] + w01 * p00[3] + w10 * p10[0] + w11 * p10[3];
            o1 = w00 * p00[1] + w01 * p00[4] + w10 * p10[1] + w11 * p10[4];
            o2 = w00 * p00[2] + w01 * p00[5] + w10 * p10[2] + w11 * p10[5];
        } else {
            float v00[3], v01[3], v10[3], v11[3];
            auto fetch = [&](int yi, int xi, float* v) {
                const bool val = ((unsigned)yi < (unsigned)HH) &&
                                 ((unsigned)xi < (unsigned)WW);
                const int yc = min(max(yi, 0), HH - 1);
                const int xc = min(max(xi, 0), WW - 1);
                const float m = val ? 1.0f : 0.0f;
                const float* pptr = imgb + (yc * WW + xc) * CC;
                v[0] = pptr[0] * m;
                v[1] = pptr[1] * m;
                v[2] = pptr[2] * m;
            };
            fetch(y0i,     x0i,     v00);
            fetch(y0i,     x0i + 1, v01);
            fetch(y0i + 1, x0i,     v10);
            fetch(y0i + 1, x0i + 1, v11);
            o0 = w00 * v00[0] + w01 * v01[0] + w10 * v10[0] + w11 * v11[0];
            o1 = w00 * v00[1] + w01 * v01[1] + w10 * v10[1] + w11 * v11[1];
            o2 = w00 * v00[2] + w01 * v01[2] + w10 * v10[2] + w11 * v11[2];
        }

        float* op = outb + p * CC;
        op[0] = o0; op[1] = o1; op[2] = o2;
        s0 += o0; s1 += o1; s2 += o2;
    }

    // deterministic block reduction
    __shared__ float sm[8][3];
    const int lane = t & 31;
    const int wrp  = t >> 5;
#pragma unroll
    for (int off = 16; off > 0; off >>= 1) {
        s0 += __shfl_down_sync(0xffffffffu, s0, off);
        s1 += __shfl_down_sync(0xffffffffu, s1, off);
        s2 += __shfl_down_sync(0xffffffffu, s2, off);
    }
    if (lane == 0) { sm[wrp][0] = s0; sm[wrp][1] = s1; sm[wrp][2] = s2; }
    __syncthreads();
    if (wrp == 0 && lane < 8) {
        float t0 = sm[lane][0], t1 = sm[lane][1], t2 = sm[lane][2];
#pragma unroll
        for (int off = 4; off > 0; off >>= 1) {
            t0 += __shfl_down_sync(0xffu, t0, off);
            t1 += __shfl_down_sync(0xffu, t1, off);
            t2 += __shfl_down_sync(0xffu, t2, off);
        }
        if (lane == 0) {
            g_partial[b][blk][0] = t0;
            g_partial[b][blk][1] = t1;
            g_partial[b][blk][2] = t2;
        }
    }
}

// ---------------------------------------------------------------------------
// Kernel 2: fused mean-reduce + masks + contrast/brightness + cutouts + clip
// Block = 256 thr, 8 px/thread = 2048 px = 8 rows. Grid = (32 rowgrp, 64 img).
// ---------------------------------------------------------------------------
__device__ __forceinline__ unsigned rmask(int x0, int x1, int lo)
{
    int s = x0 - lo; if (s < 0) s = 0;
    int e = x1 - lo; if (e > 32) e = 32;
    if (e <= s) return 0u;
    unsigned me = (e == 32) ? 0xffffffffu : ((1u << e) - 1u);
    unsigned ms = (s == 0)  ? 0u          : ((1u << s) - 1u);
    return me & ~ms;
}

__global__ __launch_bounds__(256) void k_epilogue(
    const float* __restrict__ contrast, const float* __restrict__ brightness,
    const float* __restrict__ fill_is_one,
    const int* __restrict__ hs, const int* __restrict__ ws,
    const int* __restrict__ y0, const int* __restrict__ x0,
    float* __restrict__ out)
{
    const int b  = blockIdx.y;
    const int rg = blockIdx.x;           // 0..31, 8 rows each
    const int t  = threadIdx.x;          // 0..255

    __shared__ int ry0[KK], ry1[KK], rx0[KK], rx1[KK], rfill[KK];
    __shared__ float smr[4][3];
    __shared__ float smean[3];
    __shared__ unsigned sew[8][8];
    __shared__ unsigned sbw[8][8];

    // phase 1: rect load (t<20) + mean partial reduce (threads 128..255)
    if (t < KK) {
        const int k  = t;
        const int hk = hs[b * KK + k];
        const int wk = ws[b * KK + k];
        int yc = y0[b * KK + k]; if (yc > HH - hk) yc = HH - hk;
        int xc = x0[b * KK + k]; if (xc > WW - wk) xc = WW - wk;
        ry0[k] = yc; ry1[k] = yc + hk;
        rx0[k] = xc; rx1[k] = xc + wk;
        rfill[k] = (fill_is_one[b * KK + k] > 0.5f) ? 1 : 0;
    }
    if (t >= 128) {
        const int tt = t - 128;          // 0..127
        float s0 = g_partial[b][tt][0];
        float s1 = g_partial[b][tt][1];
        float s2 = g_partial[b][tt][2];
        const int lane = tt & 31;
        const int wrp  = tt >> 5;        // 0..3
#pragma unroll
        for (int off = 16; off > 0; off >>= 1) {
            s0 += __shfl_down_sync(0xffffffffu, s0, off);
            s1 += __shfl_down_sync(0xffffffffu, s1, off);
            s2 += __shfl_down_sync(0xffffffffu, s2, off);
        }
        if (lane == 0) { smr[wrp][0] = s0; smr[wrp][1] = s1; smr[wrp][2] = s2; }
    }
    __syncthreads();
    if (t == 0) {
        const float inv = 1.0f / (float)HWPIX;
        smean[0] = (smr[0][0] + smr[1][0] + smr[2][0] + smr[3][0]) * inv;
        smean[1] = (smr[0][1] + smr[1][1] + smr[2][1] + smr[3][1]) * inv;
        smean[2] = (smr[0][2] + smr[1][2] + smr[2][2] + smr[3][2]) * inv;
    }
    // phase 2: build 8-row bitmasks (threads 0..63: row=t>>3, word=t&7)
    if (t < 64) {
        const int row = rg * 8 + (t >> 3);
        const int w   = t & 7;
        unsigned em = 0u, bm = 0u;
#pragma unroll
        for (int k = 0; k < KK; k++) {
            if (row >= ry0[k] && row < ry1[k]) {
                const unsigned m = rmask(rx0[k], rx1[k], w * 32);
                if (rfill[k]) bm |= m; else em |= m;
            }
        }
        sew[t >> 3][w] = em;
        sbw[t >> 3][w] = bm;
    }
    __syncthreads();

    const float m0 = smean[0];
    const float m1 = smean[1];
    const float m2 = smean[2];
    const float ct = contrast[b];
    const float br = brightness[b];

    const int p  = rg * 2048 + 8 * t;    // first pixel of this thread (8 px)
    const int yl = t >> 5;               // row within block (0..7)
    const int x  = (8 * t) & 255;        // x of first pixel (multiple of 8)

    const unsigned ew = sew[yl][x >> 5] >> (x & 31);   // 8 bits
    const unsigned bw = sbw[yl][x >> 5] >> (x & 31);

    float4* base = (float4*)(out + ((size_t)b * HWPIX + p) * CC);
    // 6 independent loads (front-batched -> MLP 6)
    float4 f0 = base[0];
    float4 f1 = base[1];
    float4 f2 = base[2];
    float4 f3 = base[3];
    float4 f4 = base[4];
    float4 f5 = base[5];

    float v[24] = { f0.x, f0.y, f0.z, f0.w, f1.x, f1.y, f1.z, f1.w,
                    f2.x, f2.y, f2.z, f2.w, f3.x, f3.y, f3.z, f3.w,
                    f4.x, f4.y, f4.z, f4.w, f5.x, f5.y, f5.z, f5.w };
    const float mm[3] = { m0, m1, m2 };

#pragma unroll
    for (int j = 0; j < 24; j++) {
        const int ch = j % 3;
        const int px = j / 3;            // 0..7
        float val = (v[j] - mm[ch]) * ct + mm[ch] + br;
        if ((ew >> px) & 1u) val = 0.0f;
        if ((bw >> px) & 1u) val = 1.0f;
        v[j] = fminf(fmaxf(val, 0.0f), 1.0f);
    }

    base[0] = make_float4(v[0],  v[1],  v[2],  v[3]);
    base[1] = make_float4(v[4],  v[5],  v[6],  v[7]);
    base[2] = make_float4(v[8],  v[9],  v[10], v[11]);
    base[3] = make_float4(v[12], v[13], v[14], v[15]);
    base[4] = make_float4(v[16], v[17], v[18], v[19]);
    base[5] = make_float4(v[20], v[21], v[22], v[23]);
}

// ---------------------------------------------------------------------------
extern "C" void kernel_launch(void* const* d_in, const int* in_sizes, int n_in,
                              void* d_out, int out_size)
{
    const float* images     = (const float*)d_in[0];
    const float* zoom       = (const float*)d_in[1];
    const float* rot        = (const float*)d_in[2];
    const float* shy        = (const float*)d_in[3];
    const float* ty         = (const float*)d_in[4];
    const float* tx         = (const float*)d_in[5];
    const float* contrast   = (const float*)d_in[6];
    const float* brightness = (const float*)d_in[7];
    const float* fill       = (const float*)d_in[8];
    const int*   hs         = (const int*)d_in[9];
    const int*   ws         = (const int*)d_in[10];
    const int*   y0         = (const int*)d_in[11];
    const int*   x0         = (const int*)d_in[12];
    float* out = (float*)d_out;

    dim3 gwarp(WBLK_PER_IMG, BB);
    k_warp<<<gwarp, 256>>>(images, zoom, rot, shy, ty, tx, out);
    dim3 gepi(32, BB);
    k_epilogue<<<gepi, 256>>>(contrast, brightness, fill, hs, ws, y0, x0, out);
}

// round 7
// speedup vs baseline: 1.6992x; 1.6992x over previous
#include <cuda_runtime.h>

#define BB 64
#define HH 256
#define WW 256
#define CC 3
#define KK 20
#define HWPIX (HH * WW)
#define WBLK_PER_IMG 128   // k_warp: each block covers 2 rows (512 pixels)

// Scratch (device global: allowed, no allocation)
__device__ float g_partial[BB][WBLK_PER_IMG][3];

// ---------------------------------------------------------------------------
// Kernel 1: direct-gather affine bilinear warp + per-block partial sums
// Interior fast path removes per-corner valid/clamp ALU for ~97% of pixels.
// ---------------------------------------------------------------------------
__global__ __launch_bounds__(256) void k_warp(
    const float* __restrict__ img,
    const float* __restrict__ zoom, const float* __restrict__ rot,
    const float* __restrict__ shy,  const float* __restrict__ ty,
    const float* __restrict__ tx,
    float* __restrict__ out)
{
    const int b   = blockIdx.y;
    const int blk = blockIdx.x;          // 0..127
    const int t   = threadIdx.x;         // 0..255

    const float z  = zoom[b];
    const float r  = rot[b];
    const float sh = shy[b];
    const float co = cosf(r), si = sinf(r);
    const float a0 = z * co;
    const float a1 = -z * (si + sh);
    const float b0 = z * si;
    const float b1 = z * co;
    const float cx = (WW - 1) * 0.5f, cy = (HH - 1) * 0.5f;
    const float a2 = -a0 * cx - a1 * cy + cx + tx[b];
    const float b2 = -b0 * cx - b1 * cy + cy + ty[b];

    const float* __restrict__ imgb = img + (size_t)b * HWPIX * CC;
    float* __restrict__ outb = out + (size_t)b * HWPIX * CC;

    float s0 = 0.f, s1 = 0.f, s2 = 0.f;

#pragma unroll
    for (int pp = 0; pp < 2; pp++) {
        const int p = blk * 512 + pp * 256 + t;   // pixel index within image
        const int y = p >> 8;                     // W == 256
        const int x = p & 255;

        const float xf = (float)x, yf = (float)y;
        const float xs = a0 * xf + a1 * yf + a2;
        const float ys = b0 * xf + b1 * yf + b2;
        const float x0f = floorf(xs);
        const float y0f = floorf(ys);
        const float wx = xs - x0f;
        const float wy = ys - y0f;
        const int x0i = (int)x0f;
        const int y0i = (int)y0f;

        const float w00 = (1.f - wy) * (1.f - wx);
        const float w01 = (1.f - wy) * wx;
        const float w10 = wy * (1.f - wx);
        const float w11 = wy * wx;

        float o0, o1, o2;

        const bool interior = (x0i >= 0) & (y0i >= 0) &
                              (x0i < WW - 1) & (y0i < HH - 1);
        if (interior) {
            const float* p00 = imgb + (y0i * WW + x0i) * CC;
            const float* p10 = p00 + WW * CC;
            o0 = w00 * p00[0] + w01 * p00[3] + w10 * p10[0] + w11 * p10[3];
            o1 = w00 * p00[1] + w01 * p00[4] + w10 * p10[1] + w11 * p10[4];
            o2 = w00 * p00[2] + w01 * p00[5] + w10 * p10[2] + w11 * p10[5];
        } else {
            float v00[3], v01[3], v10[3], v11[3];
            auto fetch = [&](int yi, int xi, float* v) {
                const bool val = ((unsigned)yi < (unsigned)HH) &&
                                 ((unsigned)xi < (unsigned)WW);
                const int yc = min(max(yi, 0), HH - 1);
                const int xc = min(max(xi, 0), WW - 1);
                const float m = val ? 1.0f : 0.0f;
                const float* pptr = imgb + (yc * WW + xc) * CC;
                v[0] = pptr[0] * m;
                v[1] = pptr[1] * m;
                v[2] = pptr[2] * m;
            };
            fetch(y0i,     x0i,     v00);
            fetch(y0i,     x0i + 1, v01);
            fetch(y0i + 1, x0i,     v10);
            fetch(y0i + 1, x0i + 1, v11);
            o0 = w00 * v00[0] + w01 * v01[0] + w10 * v10[0] + w11 * v11[0];
            o1 = w00 * v00[1] + w01 * v01[1] + w10 * v10[1] + w11 * v11[1];
            o2 = w00 * v00[2] + w01 * v01[2] + w10 * v10[2] + w11 * v11[2];
        }

        float* op = outb + p * CC;
        op[0] = o0; op[1] = o1; op[2] = o2;
        s0 += o0; s1 += o1; s2 += o2;
    }

    // deterministic block reduction
    __shared__ float sm[8][3];
    const int lane = t & 31;
    const int wrp  = t >> 5;
#pragma unroll
    for (int off = 16; off > 0; off >>= 1) {
        s0 += __shfl_down_sync(0xffffffffu, s0, off);
        s1 += __shfl_down_sync(0xffffffffu, s1, off);
        s2 += __shfl_down_sync(0xffffffffu, s2, off);
    }
    if (lane == 0) { sm[wrp][0] = s0; sm[wrp][1] = s1; sm[wrp][2] = s2; }
    __syncthreads();
    if (wrp == 0 && lane < 8) {
        float t0 = sm[lane][0], t1 = sm[lane][1], t2 = sm[lane][2];
#pragma unroll
        for (int off = 4; off > 0; off >>= 1) {
            t0 += __shfl_down_sync(0xffu, t0, off);
            t1 += __shfl_down_sync(0xffu, t1, off);
            t2 += __shfl_down_sync(0xffu, t2, off);
        }
        if (lane == 0) {
            g_partial[b][blk][0] = t0;
            g_partial[b][blk][1] = t1;
            g_partial[b][blk][2] = t2;
        }
    }
}

// ---------------------------------------------------------------------------
// Kernel 2: fused mean-reduce + float-expanded masks + contrast + cutouts
// Block covers 4 rows = 768 float4. Thread t handles float4 {t, t+256, t+512}
// -> every LDG.128 / STG.128 is lane-consecutive (perfectly coalesced).
// ---------------------------------------------------------------------------
__device__ __forceinline__ unsigned rmask(int f0, int f1, int lo)
{
    int s = f0 - lo; if (s < 0) s = 0;
    int e = f1 - lo; if (e > 32) e = 32;
    if (e <= s) return 0u;
    unsigned me = (e == 32) ? 0xffffffffu : ((1u << e) - 1u);
    unsigned ms = (s == 0)  ? 0u          : ((1u << s) - 1u);
    return me & ~ms;
}

__global__ __launch_bounds__(256) void k_epilogue(
    const float* __restrict__ contrast, const float* __restrict__ brightness,
    const float* __restrict__ fill_is_one,
    const int* __restrict__ hs, const int* __restrict__ ws,
    const int* __restrict__ y0, const int* __restrict__ x0,
    float* __restrict__ out)
{
    const int b  = blockIdx.y;
    const int rg = blockIdx.x;           // 0..63, 4 rows each
    const int t  = threadIdx.x;          // 0..255

    __shared__ int ry0[KK], ry1[KK], rf0[KK], rf1[KK], rfill[KK];
    __shared__ float smr[4][3];
    __shared__ float soff[3];
    __shared__ unsigned sem[4][24];      // float-expanded erase masks (768 bits/row)
    __shared__ unsigned sbm[4][24];      // float-expanded blot masks

    // phase 1: rect load (t<20) + mean partial reduce (threads 128..255)
    if (t < KK) {
        const int k  = t;
        const int hk = hs[b * KK + k];
        const int wk = ws[b * KK + k];
        int yc = y0[b * KK + k]; if (yc > HH - hk) yc = HH - hk;
        int xc = x0[b * KK + k]; if (xc > WW - wk) xc = WW - wk;
        ry0[k] = yc; ry1[k] = yc + hk;
        rf0[k] = 3 * xc; rf1[k] = 3 * (xc + wk);   // float-index range in row
        rfill[k] = (fill_is_one[b * KK + k] > 0.5f) ? 1 : 0;
    }
    if (t >= 128) {
        const int tt = t - 128;          // 0..127
        float s0 = g_partial[b][tt][0];
        float s1 = g_partial[b][tt][1];
        float s2 = g_partial[b][tt][2];
        const int lane = tt & 31;
        const int wrp  = tt >> 5;        // 0..3
#pragma unroll
        for (int off = 16; off > 0; off >>= 1) {
            s0 += __shfl_down_sync(0xffffffffu, s0, off);
            s1 += __shfl_down_sync(0xffffffffu, s1, off);
            s2 += __shfl_down_sync(0xffffffffu, s2, off);
        }
        if (lane == 0) { smr[wrp][0] = s0; smr[wrp][1] = s1; smr[wrp][2] = s2; }
    }
    __syncthreads();
    if (t == 0) {
        const float inv = 1.0f / (float)HWPIX;
        const float ctv = contrast[b];
        const float brv = brightness[b];
        const float m0 = (smr[0][0] + smr[1][0] + smr[2][0] + smr[3][0]) * inv;
        const float m1 = (smr[0][1] + smr[1][1] + smr[2][1] + smr[3][1]) * inv;
        const float m2 = (smr[0][2] + smr[1][2] + smr[2][2] + smr[3][2]) * inv;
        // (v - m)*ct + m + br == v*ct + (m*(1-ct) + br)
        soff[0] = m0 * (1.0f - ctv) + brv;
        soff[1] = m1 * (1.0f - ctv) + brv;
        soff[2] = m2 * (1.0f - ctv) + brv;
    }
    // phase 2: build float-expanded masks (threads 0..95: row=t/24, word=t%24)
    if (t < 96) {
        const int rl = t / 24;
        const int w  = t - rl * 24;
        const int row = rg * 4 + rl;
        unsigned em = 0u, bm = 0u;
#pragma unroll
        for (int k = 0; k < KK; k++) {
            if (row >= ry0[k] && row < ry1[k]) {
                const unsigned m = rmask(rf0[k], rf1[k], w * 32);
                if (rfill[k]) bm |= m; else em |= m;
            }
        }
        sem[rl][w] = em;
        sbm[rl][w] = bm;
    }
    __syncthreads();

    const float ctv = contrast[b];
    const float o0 = soff[0], o1 = soff[1], o2 = soff[2];

    float4* base = (float4*)(out + (size_t)b * HWPIX * CC + (size_t)rg * 3072);

    // front-batched coalesced loads
    const int q0 = t, q1 = t + 256, q2 = t + 512;
    float4 va = base[q0];
    float4 vb = base[q1];
    float4 vc = base[q2];

    auto process = [&](float4 v, int q) -> float4 {
        const int rl  = q / 192;                 // row within block (0..3)
        const int fr  = (q - rl * 192) * 4;      // float index within row [0,768)
        const unsigned e4 = (sem[rl][fr >> 5] >> (fr & 31)) & 15u;
        const unsigned b4 = (sbm[rl][fr >> 5] >> (fr & 31)) & 15u;
        const int sel = q % 3;                   // channel of element 0
        const float ox = (sel == 0) ? o0 : ((sel == 1) ? o1 : o2);
        const float oy = (sel == 0) ? o1 : ((sel == 1) ? o2 : o0);
        const float oz = (sel == 0) ? o2 : ((sel == 1) ? o0 : o1);
        // element 3 has channel (q+3)%3 == q%3 -> same offset as element 0
        float x = v.x * ctv + ox;
        float y = v.y * ctv + oy;
        float z = v.z * ctv + oz;
        float w = v.w * ctv + ox;
        if (e4 & 1u) x = 0.f;
        if (e4 & 2u) y = 0.f;
        if (e4 & 4u) z = 0.f;
        if (e4 & 8u) w = 0.f;
        if (b4 & 1u) x = 1.f;
        if (b4 & 2u) y = 1.f;
        if (b4 & 4u) z = 1.f;
        if (b4 & 8u) w = 1.f;
        x = fminf(fmaxf(x, 0.f), 1.f);
        y = fminf(fmaxf(y, 0.f), 1.f);
        z = fminf(fmaxf(z, 0.f), 1.f);
        w = fminf(fmaxf(w, 0.f), 1.f);
        return make_float4(x, y, z, w);
    };

    base[q0] = process(va, q0);
    base[q1] = process(vb, q1);
    base[q2] = process(vc, q2);
}

// ---------------------------------------------------------------------------
extern "C" void kernel_launch(void* const* d_in, const int* in_sizes, int n_in,
                              void* d_out, int out_size)
{
    const float* images     = (const float*)d_in[0];
    const float* zoom       = (const float*)d_in[1];
    const float* rot        = (const float*)d_in[2];
    const float* shy        = (const float*)d_in[3];
    const float* ty         = (const float*)d_in[4];
    const float* tx         = (const float*)d_in[5];
    const float* contrast   = (const float*)d_in[6];
    const float* brightness = (const float*)d_in[7];
    const float* fill       = (const float*)d_in[8];
    const int*   hs         = (const int*)d_in[9];
    const int*   ws         = (const int*)d_in[10];
    const int*   y0         = (const int*)d_in[11];
    const int*   x0         = (const int*)d_in[12];
    float* out = (float*)d_out;

    dim3 gwarp(WBLK_PER_IMG, BB);
    k_warp<<<gwarp, 256>>>(images, zoom, rot, shy, ty, tx, out);
    dim3 gepi(64, BB);
    k_epilogue<<<gepi, 256>>>(contrast, brightness, fill, hs, ws, y0, x0, out);
}

// round 8
// speedup vs baseline: 1.7139x; 1.0086x over previous
#include <cuda_runtime.h>

#define BB 64
#define HH 256
#define WW 256
#define CC 3
#define KK 20
#define HWPIX (HH * WW)
#define WBLK_PER_IMG 128   // k_warp: each block covers 2 rows (512 pixels)

// Scratch (device global: allowed, no allocation)
__device__ float g_partial[BB][WBLK_PER_IMG][3];

// ---------------------------------------------------------------------------
// Kernel 1: direct-gather affine bilinear warp + per-block partial sums
// Interior fast path removes per-corner valid/clamp ALU for ~97% of pixels.
// (unchanged from R7 — proven ~25 us, L1-wavefront bound by RGB layout)
// ---------------------------------------------------------------------------
__global__ __launch_bounds__(256) void k_warp(
    const float* __restrict__ img,
    const float* __restrict__ zoom, const float* __restrict__ rot,
    const float* __restrict__ shy,  const float* __restrict__ ty,
    const float* __restrict__ tx,
    float* __restrict__ out)
{
    const int b   = blockIdx.y;
    const int blk = blockIdx.x;          // 0..127
    const int t   = threadIdx.x;         // 0..255

    const float z  = zoom[b];
    const float r  = rot[b];
    const float sh = shy[b];
    const float co = cosf(r), si = sinf(r);
    const float a0 = z * co;
    const float a1 = -z * (si + sh);
    const float b0 = z * si;
    const float b1 = z * co;
    const float cx = (WW - 1) * 0.5f, cy = (HH - 1) * 0.5f;
    const float a2 = -a0 * cx - a1 * cy + cx + tx[b];
    const float b2 = -b0 * cx - b1 * cy + cy + ty[b];

    const float* __restrict__ imgb = img + (size_t)b * HWPIX * CC;
    float* __restrict__ outb = out + (size_t)b * HWPIX * CC;

    float s0 = 0.f, s1 = 0.f, s2 = 0.f;

#pragma unroll
    for (int pp = 0; pp < 2; pp++) {
        const int p = blk * 512 + pp * 256 + t;   // pixel index within image
        const int y = p >> 8;                     // W == 256
        const int x = p & 255;

        const float xf = (float)x, yf = (float)y;
        const float xs = a0 * xf + a1 * yf + a2;
        const float ys = b0 * xf + b1 * yf + b2;
        const float x0f = floorf(xs);
        const float y0f = floorf(ys);
        const float wx = xs - x0f;
        const float wy = ys - y0f;
        const int x0i = (int)x0f;
        const int y0i = (int)y0f;

        const float w00 = (1.f - wy) * (1.f - wx);
        const float w01 = (1.f - wy) * wx;
        const float w10 = wy * (1.f - wx);
        const float w11 = wy * wx;

        float o0, o1, o2;

        const bool interior = (x0i >= 0) & (y0i >= 0) &
                              (x0i < WW - 1) & (y0i < HH - 1);
        if (interior) {
            const float* p00 = imgb + (y0i * WW + x0i) * CC;
            const float* p10 = p00 + WW * CC;
            o0 = w00 * p00[0] + w01 * p00[3] + w10 * p10[0] + w11 * p10[3];
            o1 = w00 * p00[1] + w01 * p00[4] + w10 * p10[1] + w11 * p10[4];
            o2 = w00 * p00[2] + w01 * p00[5] + w10 * p10[2] + w11 * p10[5];
        } else {
            float v00[3], v01[3], v10[3], v11[3];
            auto fetch = [&](int yi, int xi, float* v) {
                const bool val = ((unsigned)yi < (unsigned)HH) &&
                                 ((unsigned)xi < (unsigned)WW);
                const int yc = min(max(yi, 0), HH - 1);
                const int xc = min(max(xi, 0), WW - 1);
                const float m = val ? 1.0f : 0.0f;
                const float* pptr = imgb + (yc * WW + xc) * CC;
                v[0] = pptr[0] * m;
                v[1] = pptr[1] * m;
                v[2] = pptr[2] * m;
            };
            fetch(y0i,     x0i,     v00);
            fetch(y0i,     x0i + 1, v01);
            fetch(y0i + 1, x0i,     v10);
            fetch(y0i + 1, x0i + 1, v11);
            o0 = w00 * v00[0] + w01 * v01[0] + w10 * v10[0] + w11 * v11[0];
            o1 = w00 * v00[1] + w01 * v01[1] + w10 * v10[1] + w11 * v11[1];
            o2 = w00 * v00[2] + w01 * v01[2] + w10 * v10[2] + w11 * v11[2];
        }

        float* op = outb + p * CC;
        op[0] = o0; op[1] = o1; op[2] = o2;
        s0 += o0; s1 += o1; s2 += o2;
    }

    // deterministic block reduction
    __shared__ float sm[8][3];
    const int lane = t & 31;
    const int wrp  = t >> 5;
#pragma unroll
    for (int off = 16; off > 0; off >>= 1) {
        s0 += __shfl_down_sync(0xffffffffu, s0, off);
        s1 += __shfl_down_sync(0xffffffffu, s1, off);
        s2 += __shfl_down_sync(0xffffffffu, s2, off);
    }
    if (lane == 0) { sm[wrp][0] = s0; sm[wrp][1] = s1; sm[wrp][2] = s2; }
    __syncthreads();
    if (wrp == 0 && lane < 8) {
        float t0 = sm[lane][0], t1 = sm[lane][1], t2 = sm[lane][2];
#pragma unroll
        for (int off = 4; off > 0; off >>= 1) {
            t0 += __shfl_down_sync(0xffu, t0, off);
            t1 += __shfl_down_sync(0xffu, t1, off);
            t2 += __shfl_down_sync(0xffu, t2, off);
        }
        if (lane == 0) {
            g_partial[b][blk][0] = t0;
            g_partial[b][blk][1] = t1;
            g_partial[b][blk][2] = t2;
        }
    }
}

// ---------------------------------------------------------------------------
// Kernel 2: fused mean-reduce + float-expanded masks + contrast + cutouts
// Block covers 8 rows = 1536 float4. Thread t handles float4 {t + 256k},
// k=0..5 -> every LDG.128 / STG.128 is lane-consecutive. MLP 6.
// ---------------------------------------------------------------------------
__device__ __forceinline__ unsigned rmask(int f0, int f1, int lo)
{
    int s = f0 - lo; if (s < 0) s = 0;
    int e = f1 - lo; if (e > 32) e = 32;
    if (e <= s) return 0u;
    unsigned me = (e == 32) ? 0xffffffffu : ((1u << e) - 1u);
    unsigned ms = (s == 0)  ? 0u          : ((1u << s) - 1u);
    return me & ~ms;
}

__global__ __launch_bounds__(256) void k_epilogue(
    const float* __restrict__ contrast, const float* __restrict__ brightness,
    const float* __restrict__ fill_is_one,
    const int* __restrict__ hs, const int* __restrict__ ws,
    const int* __restrict__ y0, const int* __restrict__ x0,
    float* __restrict__ out)
{
    const int b  = blockIdx.y;
    const int rg = blockIdx.x;           // 0..31, 8 rows each
    const int t  = threadIdx.x;          // 0..255

    __shared__ int ry0[KK], ry1[KK], rf0[KK], rf1[KK], rfill[KK];
    __shared__ float smr[2][3];
    __shared__ float soff[3];
    __shared__ unsigned sem[8][24];      // float-expanded erase masks (768b/row)
    __shared__ unsigned sbm[8][24];      // float-expanded blot masks

    // phase A: rect load (t<20) + partial-sum gather (threads 192..255)
    if (t < KK) {
        const int k  = t;
        const int hk = hs[b * KK + k];
        const int wk = ws[b * KK + k];
        int yc = y0[b * KK + k]; if (yc > HH - hk) yc = HH - hk;
        int xc = x0[b * KK + k]; if (xc > WW - wk) xc = WW - wk;
        ry0[k] = yc; ry1[k] = yc + hk;
        rf0[k] = 3 * xc; rf1[k] = 3 * (xc + wk);   // float-index range in row
        rfill[k] = (fill_is_one[b * KK + k] > 0.5f) ? 1 : 0;
    }
    if (t >= 192) {
        const int tt = t - 192;          // 0..63 -> partials tt and tt+64
        float s0 = g_partial[b][tt][0] + g_partial[b][tt + 64][0];
        float s1 = g_partial[b][tt][1] + g_partial[b][tt + 64][1];
        float s2 = g_partial[b][tt][2] + g_partial[b][tt + 64][2];
        const int lane = tt & 31;
        const int wrp  = tt >> 5;        // 0..1
#pragma unroll
        for (int off = 16; off > 0; off >>= 1) {
            s0 += __shfl_down_sync(0xffffffffu, s0, off);
            s1 += __shfl_down_sync(0xffffffffu, s1, off);
            s2 += __shfl_down_sync(0xffffffffu, s2, off);
        }
        if (lane == 0) { smr[wrp][0] = s0; smr[wrp][1] = s1; smr[wrp][2] = s2; }
    }
    __syncthreads();

    // phase B: masks (threads 0..191) + mean finalize (t==192)
    if (t < 192) {
        const int rl = t / 24;           // 0..7
        const int w  = t - rl * 24;      // 0..23
        const int row = rg * 8 + rl;
        unsigned em = 0u, bm = 0u;
#pragma unroll
        for (int k = 0; k < KK; k++) {
            if (row >= ry0[k] && row < ry1[k]) {
                const unsigned m = rmask(rf0[k], rf1[k], w * 32);
                if (rfill[k]) bm |= m; else em |= m;
            }
        }
        sem[rl][w] = em;
        sbm[rl][w] = bm;
    }
    if (t == 192) {
        const float inv = 1.0f / (float)HWPIX;
        const float ctv = contrast[b];
        const float brv = brightness[b];
        const float m0 = (smr[0][0] + smr[1][0]) * inv;
        const float m1 = (smr[0][1] + smr[1][1]) * inv;
        const float m2 = (smr[0][2] + smr[1][2]) * inv;
        // (v - m)*ct + m + br == v*ct + (m*(1-ct) + br)
        soff[0] = m0 * (1.0f - ctv) + brv;
        soff[1] = m1 * (1.0f - ctv) + brv;
        soff[2] = m2 * (1.0f - ctv) + brv;
    }
    __syncthreads();

    const float ctv = contrast[b];
    const float o0 = soff[0], o1 = soff[1], o2 = soff[2];

    float4* base = (float4*)(out + (size_t)b * HWPIX * CC + (size_t)rg * 6144);

    // front-batched coalesced loads: q_k = t + 256k, k=0..5 (MLP 6)
    float4 v[6];
#pragma unroll
    for (int k = 0; k < 6; k++) v[k] = base[t + 256 * k];

    // channel phase: channel of element0 of q is q%3; 256 ≡ 1 (mod 3)
    // so access k has phase (t + k) % 3.
    const int sel0 = t % 3;

#pragma unroll
    for (int k = 0; k < 6; k++) {
        const int q   = t + 256 * k;
        const int rl  = q / 192;                 // row within block (0..7)
        const int fr  = (q - rl * 192) * 4;      // float index within row
        const unsigned e4 = (sem[rl][fr >> 5] >> (fr & 31)) & 15u;
        const unsigned b4 = (sbm[rl][fr >> 5] >> (fr & 31)) & 15u;
        int sel = sel0 + k;
        sel -= (sel >= 3) * 3;
        sel -= (sel >= 3) * 3;                   // (sel0+k) % 3, k<=5
        const float ox = (sel == 0) ? o0 : ((sel == 1) ? o1 : o2);
        const float oy = (sel == 0) ? o1 : ((sel == 1) ? o2 : o0);
        const float oz = (sel == 0) ? o2 : ((sel == 1) ? o0 : o1);
        float x = v[k].x * ctv + ox;
        float y = v[k].y * ctv + oy;
        float z = v[k].z * ctv + oz;
        float w = v[k].w * ctv + ox;             // elem3 channel == elem0 channel
        if (e4 & 1u) x = 0.f;
        if (e4 & 2u) y = 0.f;
        if (e4 & 4u) z = 0.f;
        if (e4 & 8u) w = 0.f;
        if (b4 & 1u) x = 1.f;
        if (b4 & 2u) y = 1.f;
        if (b4 & 4u) z = 1.f;
        if (b4 & 8u) w = 1.f;
        x = fminf(fmaxf(x, 0.f), 1.f);
        y = fminf(fmaxf(y, 0.f), 1.f);
        z = fminf(fmaxf(z, 0.f), 1.f);
        w = fminf(fmaxf(w, 0.f), 1.f);
        v[k] = make_float4(x, y, z, w);
    }

#pragma unroll
    for (int k = 0; k < 6; k++) base[t + 256 * k] = v[k];
}

// ---------------------------------------------------------------------------
extern "C" void kernel_launch(void* const* d_in, const int* in_sizes, int n_in,
                              void* d_out, int out_size)
{
    const float* images     = (const float*)d_in[0];
    const float* zoom       = (const float*)d_in[1];
    const float* rot        = (const float*)d_in[2];
    const float* shy        = (const float*)d_in[3];
    const float* ty         = (const float*)d_in[4];
    const float* tx         = (const float*)d_in[5];
    const float* contrast   = (const float*)d_in[6];
    const float* brightness = (const float*)d_in[7];
    const float* fill       = (const float*)d_in[8];
    const int*   hs         = (const int*)d_in[9];
    const int*   ws         = (const int*)d_in[10];
    const int*   y0         = (const int*)d_in[11];
    const int*   x0         = (const int*)d_in[12];
    float* out = (float*)d_out;

    dim3 gwarp(WBLK_PER_IMG, BB);
    k_warp<<<gwarp, 256>>>(images, zoom, rot, shy, ty, tx, out);
    dim3 gepi(32, BB);
    k_epilogue<<<gepi, 256>>>(contrast, brightness, fill, hs, ws, y0, x0, out);
}